// round 3
// baseline (speedup 1.0000x reference)
#include <cuda_runtime.h>
#include <math.h>

#define TWO_PI_F   6.283185307179586f
#define INV_TWO_PI 0.15915494309189535f
#define NT      12
#define KMIX    16
#define HDIM    256
#define LLEN    3072
#define BATCH   64
#define NSITES  1024          // LLEN / 3
#define TM      32            // sites per CTA
#define THREADS 256
#define CHUNKS  (NSITES / TM)             // 32
#define CTAS    (BATCH * CHUNKS)          // 2048
#define EPSF    1e-6f

typedef unsigned long long ull;

// Scratch (no allocations allowed)
__device__ float g_z[BATCH * LLEN];
__device__ float g_part[NT * CTAS];

__device__ __forceinline__ float mod2pi(float x) {
    float r = fmodf(x, TWO_PI_F);
    return (r < 0.f) ? r + TWO_PI_F : r;
}

__device__ __forceinline__ float tanh_fast(float x) {
    float y;
    asm("tanh.approx.f32 %0, %1;" : "=f"(y) : "f"(x));
    return y;
}

// duplicate a scalar into both lanes of an f32x2
__device__ __forceinline__ ull dup2(float x) {
    ull r;
    asm("mov.b64 %0, {%1, %1};" : "=l"(r) : "f"(x));
    return r;
}
// packed fp32 fma: a = b*c + a (elementwise on 2 lanes)
__device__ __forceinline__ void fma2(ull& a, ull b, ull c) {
    asm("fma.rn.f32x2 %0, %1, %2, %0;" : "+l"(a) : "l"(b), "l"(c));
}
__device__ __forceinline__ float2 unpk(ull v) {
    float2 f;
    asm("mov.b64 {%0, %1}, %2;" : "=f"(f.x), "=f"(f.y) : "l"(v));
    return f;
}

__global__ void init_kernel(const float* __restrict__ z_in) {
    int i = blockIdx.x * blockDim.x + threadIdx.x;
    if (i < BATCH * LLEN) g_z[i] = z_in[i];
}

__global__ __launch_bounds__(THREADS)
void step_kernel(const float* __restrict__ W1, const float* __restrict__ b1,
                 const float* __restrict__ W2, const float* __restrict__ b2,
                 const float* __restrict__ W3, const float* __restrict__ b3,
                 int t, int off)
{
    __shared__ float hbuf[TM * HDIM];     // h1 then h2 (32 KB)
    __shared__ float pbuf[TM * 48];       // params (6 KB)
    __shared__ float c1s[TM], c2s[TM], svs[TM], dsds[TM], lgs[TM], zrs[TM];

    const int tid   = threadIdx.x;
    const int b     = blockIdx.x >> 5;          // batch
    const int chunk = blockIdx.x & 31;

    const float* W1t = W1 + t * 2 * HDIM;
    const float* b1t = b1 + t * HDIM;
    const float* W2t = W2 + (size_t)t * HDIM * HDIM;
    const float* b2t = b2 + t * HDIM;
    const float* W3t = W3 + t * HDIM * 48;
    const float* b3t = b3 + t * 48;
    const float* zrow = g_z + b * LLEN;

    // -------- phase 0: per-site context ----------
    if (tid < TM) {
        int jj  = chunk * TM + tid;
        int idx = 3 * jj + off;
        int im2 = idx - 2; if (im2 < 0) im2 += LLEN;
        int im1 = idx - 1; if (im1 < 0) im1 += LLEN;
        int ip1 = idx + 1; if (ip1 >= LLEN) ip1 -= LLEN;
        int ip2 = idx + 2; if (ip2 >= LLEN) ip2 -= LLEN;
        float zm2 = zrow[im2], zm1 = zrow[im1], z0 = zrow[idx];
        float zp1 = zrow[ip1], zp2 = zrow[ip2];
        c1s[tid] = mod2pi(zm1 - zm2);
        c2s[tid] = mod2pi(zp2 - zp1);
        float Vc = mod2pi(z0 - zm1);
        float u  = fminf(fmaxf(Vc * INV_TWO_PI, EPSF), 1.f - EPSF);
        float a  = u * u;
        float bb = (1.f - u) * (1.f - u);
        float den = a + bb;
        float sv  = a / den;
        float dsdu = 2.f * u * (1.f - u) / (den * den);
        sv = fminf(fmaxf(sv, EPSF), 1.f - EPSF);
        svs[tid]  = sv;
        dsds[tid] = dsdu;
        lgs[tid]  = logf(sv) - log1pf(-sv);
        zrs[tid]  = zm1;
    }
    __syncthreads();

    // -------- layer 1: h1[s][tid] ----------
    {
        float w0 = __ldg(&W1t[tid]);
        float w1 = __ldg(&W1t[HDIM + tid]);
        float bb = __ldg(&b1t[tid]);
        #pragma unroll
        for (int s = 0; s < TM; s++) {
            hbuf[s * HDIM + tid] = tanh_fast(fmaf(c1s[s], w0, fmaf(c2s[s], w1, bb)));
        }
    }
    __syncthreads();

    // -------- layer 2: 8 sites x 4 cols per thread (packed f32x2) ----------
    // cg = tid & 63 -> cols [4cg, 4cg+4);  sg = tid >> 6 -> sites [8sg, 8sg+8)
    {
        const int cg = tid & 63;
        const int sg = tid >> 6;
        const int col = 4 * cg;
        ull acc[8][2];
        {
            ulonglong2 bb2 = *(const ulonglong2*)&b2t[col];
            #pragma unroll
            for (int s = 0; s < 8; s++) { acc[s][0] = bb2.x; acc[s][1] = bb2.y; }
        }
        const float* hrow = &hbuf[sg * 8 * HDIM];
        for (int i = 0; i < HDIM; i += 4) {
            ulonglong2 w0 = *(const ulonglong2*)&W2t[(i + 0) * HDIM + col];
            ulonglong2 w1 = *(const ulonglong2*)&W2t[(i + 1) * HDIM + col];
            ulonglong2 w2 = *(const ulonglong2*)&W2t[(i + 2) * HDIM + col];
            ulonglong2 w3 = *(const ulonglong2*)&W2t[(i + 3) * HDIM + col];
            #pragma unroll
            for (int s = 0; s < 8; s++) {
                const float4 h = *(const float4*)&hrow[s * HDIM + i];
                ull hx = dup2(h.x), hy = dup2(h.y), hz = dup2(h.z), hw = dup2(h.w);
                fma2(acc[s][0], hx, w0.x); fma2(acc[s][1], hx, w0.y);
                fma2(acc[s][0], hy, w1.x); fma2(acc[s][1], hy, w1.y);
                fma2(acc[s][0], hz, w2.x); fma2(acc[s][1], hz, w2.y);
                fma2(acc[s][0], hw, w3.x); fma2(acc[s][1], hw, w3.y);
            }
        }
        __syncthreads();   // everyone done READING h1 before overwrite
        #pragma unroll
        for (int s = 0; s < 8; s++) {
            float2 lo = unpk(acc[s][0]);
            float2 hi = unpk(acc[s][1]);
            float4 v;
            v.x = tanh_fast(lo.x);
            v.y = tanh_fast(lo.y);
            v.z = tanh_fast(hi.x);
            v.w = tanh_fast(hi.y);
            *(float4*)&hbuf[(sg * 8 + s) * HDIM + col] = v;
        }
        __syncthreads();
    }

    // -------- layer 3: 2 sites x 4 cols per thread (48 cols padded to 64) ----
    {
        const int cg3 = tid & 15;
        const int sg3 = tid >> 4;
        const int col  = 4 * cg3;
        const bool valid = (col < 48);
        const int colc = valid ? col : 0;
        ull acc3[2][2];
        {
            ulonglong2 bb2 = *(const ulonglong2*)&b3t[colc];
            #pragma unroll
            for (int q = 0; q < 2; q++) { acc3[q][0] = bb2.x; acc3[q][1] = bb2.y; }
        }
        const float* hrow = &hbuf[sg3 * 2 * HDIM];
        for (int i = 0; i < HDIM; i += 4) {
            ulonglong2 w0 = *(const ulonglong2*)&W3t[(i + 0) * 48 + colc];
            ulonglong2 w1 = *(const ulonglong2*)&W3t[(i + 1) * 48 + colc];
            ulonglong2 w2 = *(const ulonglong2*)&W3t[(i + 2) * 48 + colc];
            ulonglong2 w3 = *(const ulonglong2*)&W3t[(i + 3) * 48 + colc];
            #pragma unroll
            for (int q = 0; q < 2; q++) {
                const float4 h = *(const float4*)&hrow[q * HDIM + i];
                ull hx = dup2(h.x), hy = dup2(h.y), hz = dup2(h.z), hw = dup2(h.w);
                fma2(acc3[q][0], hx, w0.x); fma2(acc3[q][1], hx, w0.y);
                fma2(acc3[q][0], hy, w1.x); fma2(acc3[q][1], hy, w1.y);
                fma2(acc3[q][0], hz, w2.x); fma2(acc3[q][1], hz, w2.y);
                fma2(acc3[q][0], hw, w3.x); fma2(acc3[q][1], hw, w3.y);
            }
        }
        if (valid) {
            #pragma unroll
            for (int q = 0; q < 2; q++) {
                float2 lo = unpk(acc3[q][0]);
                float2 hi = unpk(acc3[q][1]);
                float4 v;
                v.x = lo.x; v.y = lo.y; v.z = hi.x; v.w = hi.y;
                *(float4*)&pbuf[(sg3 * 2 + q) * 48 + col] = v;
            }
        }
    }
    __syncthreads();

    // -------- epilogue: mixture transform, one thread per site ----------
    float ldj = 0.f;
    if (tid < TM) {
        const int s = tid;
        const float* pr = &pbuf[s * 48];
        float lgt = lgs[s], sv = svs[s];
        float m = -1e30f;
        #pragma unroll
        for (int k = 0; k < KMIX; k++) m = fmaxf(m, pr[32 + k]);
        float es[KMIX]; float se = 0.f;
        #pragma unroll
        for (int k = 0; k < KMIX; k++) { es[k] = __expf(pr[32 + k] - m); se += es[k]; }
        float inv_se = 1.f / se;
        float y = 0.f, dsum = 0.f;
        #pragma unroll
        for (int k = 0; k < KMIX; k++) {
            float wgt   = fmaf(es[k] * inv_se, 0.84f, 0.01f);
            float alpha = __expf(pr[k]);
            float x     = alpha * (lgt + pr[16 + k]);
            float g     = 1.f / (1.f + __expf(-x));
            y    = fmaf(wgt, g, y);
            dsum = fmaf(wgt * alpha, g * (1.f - g), dsum);
        }
        float dy_du = dsum / (sv * (1.f - sv)) * dsds[s];
        ldj = logf(dy_du);
        int jj  = chunk * TM + s;
        int idx = 3 * jj + off;
        g_z[b * LLEN + idx] = mod2pi(fmaf(TWO_PI_F, y, zrs[s]));
    }
    // deterministic warp reduce (tid<32 == warp 0)
    if (tid < 32) {
        #pragma unroll
        for (int o = 16; o; o >>= 1) ldj += __shfl_down_sync(0xffffffff, ldj, o);
        if (tid == 0) g_part[t * CTAS + blockIdx.x] = ldj;
    }
}

__global__ void final_kernel(float* __restrict__ out, int out_size) {
    int i = blockIdx.x * blockDim.x + threadIdx.x;
    if (i < BATCH * LLEN && i < out_size) out[i] = g_z[i];
    if (blockIdx.x == 0 && threadIdx.x < BATCH) {
        int o = BATCH * LLEN + threadIdx.x;
        if (o < out_size) {
            float s = 0.f;
            for (int t = 0; t < NT; t++)
                for (int c = 0; c < CHUNKS; c++)
                    s += g_part[t * CTAS + threadIdx.x * CHUNKS + c];
            out[o] = s;
        }
    }
}

extern "C" void kernel_launch(void* const* d_in, const int* in_sizes, int n_in,
                              void* d_out, int out_size) {
    const float* z  = (const float*)d_in[0];
    const float* W1 = (const float*)d_in[1];
    const float* b1 = (const float*)d_in[2];
    const float* W2 = (const float*)d_in[3];
    const float* b2 = (const float*)d_in[4];
    const float* W3 = (const float*)d_in[5];
    const float* b3 = (const float*)d_in[6];
    float* out = (float*)d_out;

    init_kernel<<<(BATCH * LLEN + 255) / 256, 256>>>(z);
    for (int t = 0; t < NT; t++) {
        const int off_tab[3] = {0, 2, 1};
        int off = off_tab[t % 3];
        step_kernel<<<CTAS, THREADS>>>(W1, b1, W2, b2, W3, b3, t, off);
    }
    final_kernel<<<(BATCH * LLEN + 255) / 256, 256>>>(out, out_size);
}

// round 4
// speedup vs baseline: 1.0019x; 1.0019x over previous
#include <cuda_runtime.h>
#include <math.h>

#define TWO_PI_F   6.283185307179586f
#define INV_TWO_PI 0.15915494309189535f
#define NT      12
#define KMIX    16
#define HDIM    256
#define LLEN    3072
#define BATCH   64
#define NSITES  1024          // LLEN / 3
#define TM      32            // sites per CTA
#define THREADS 256
#define CHUNKS  (NSITES / TM)             // 32
#define CTAS    (BATCH * CHUNKS)          // 2048
#define EPSF    1e-6f

typedef unsigned long long ull;

// Scratch (no allocations allowed)
__device__ float g_z[BATCH * LLEN];
__device__ float g_part[NT * CTAS];

__device__ __forceinline__ float mod2pi(float x) {
    float r = fmodf(x, TWO_PI_F);
    return (r < 0.f) ? r + TWO_PI_F : r;
}

__device__ __forceinline__ float tanh_fast(float x) {
    float y;
    asm("tanh.approx.f32 %0, %1;" : "=f"(y) : "f"(x));
    return y;
}

// duplicate a scalar into both lanes of an f32x2
__device__ __forceinline__ ull dup2(float x) {
    ull r;
    asm("mov.b64 %0, {%1, %1};" : "=l"(r) : "f"(x));
    return r;
}
// packed fp32 fma: a = b*c + a (elementwise on 2 lanes)
__device__ __forceinline__ void fma2(ull& a, ull b, ull c) {
    asm("fma.rn.f32x2 %0, %1, %2, %0;" : "+l"(a) : "l"(b), "l"(c));
}
__device__ __forceinline__ float2 unpk(ull v) {
    float2 f;
    asm("mov.b64 {%0, %1}, %2;" : "=f"(f.x), "=f"(f.y) : "l"(v));
    return f;
}

__global__ void init_kernel(const float* __restrict__ z_in) {
    int i = blockIdx.x * blockDim.x + threadIdx.x;
    if (i < BATCH * LLEN) g_z[i] = z_in[i];
}

__global__ __launch_bounds__(THREADS)
void step_kernel(const float* __restrict__ W1, const float* __restrict__ b1,
                 const float* __restrict__ W2, const float* __restrict__ b2,
                 const float* __restrict__ W3, const float* __restrict__ b3,
                 int t, int off)
{
    __shared__ float hbuf[TM * HDIM];     // h1 then h2 (32 KB)
    __shared__ float pbuf[TM * 48];       // params (6 KB)
    __shared__ float c1s[TM], c2s[TM], svs[TM], dsds[TM], lgs[TM], zrs[TM];

    const int tid   = threadIdx.x;
    const int b     = blockIdx.x >> 5;          // batch
    const int chunk = blockIdx.x & 31;

    const float* W1t = W1 + t * 2 * HDIM;
    const float* b1t = b1 + t * HDIM;
    const float* W2t = W2 + (size_t)t * HDIM * HDIM;
    const float* b2t = b2 + t * HDIM;
    const float* W3t = W3 + t * HDIM * 48;
    const float* b3t = b3 + t * 48;
    const float* zrow = g_z + b * LLEN;

    // -------- phase 0: per-site context ----------
    if (tid < TM) {
        int jj  = chunk * TM + tid;
        int idx = 3 * jj + off;
        int im2 = idx - 2; if (im2 < 0) im2 += LLEN;
        int im1 = idx - 1; if (im1 < 0) im1 += LLEN;
        int ip1 = idx + 1; if (ip1 >= LLEN) ip1 -= LLEN;
        int ip2 = idx + 2; if (ip2 >= LLEN) ip2 -= LLEN;
        float zm2 = zrow[im2], zm1 = zrow[im1], z0 = zrow[idx];
        float zp1 = zrow[ip1], zp2 = zrow[ip2];
        c1s[tid] = mod2pi(zm1 - zm2);
        c2s[tid] = mod2pi(zp2 - zp1);
        float Vc = mod2pi(z0 - zm1);
        float u  = fminf(fmaxf(Vc * INV_TWO_PI, EPSF), 1.f - EPSF);
        float a  = u * u;
        float bb = (1.f - u) * (1.f - u);
        float den = a + bb;
        float sv  = a / den;
        float dsdu = 2.f * u * (1.f - u) / (den * den);
        sv = fminf(fmaxf(sv, EPSF), 1.f - EPSF);
        svs[tid]  = sv;
        dsds[tid] = dsdu;
        lgs[tid]  = logf(sv) - log1pf(-sv);
        zrs[tid]  = zm1;
    }
    __syncthreads();

    // -------- layer 1: h1[s][tid] ----------
    {
        float w0 = __ldg(&W1t[tid]);
        float w1 = __ldg(&W1t[HDIM + tid]);
        float bb = __ldg(&b1t[tid]);
        #pragma unroll
        for (int s = 0; s < TM; s++) {
            hbuf[s * HDIM + tid] = tanh_fast(fmaf(c1s[s], w0, fmaf(c2s[s], w1, bb)));
        }
    }
    __syncthreads();

    // -------- layer 2: 8 sites x 4 cols per thread (packed f32x2) ----------
    // cg = tid & 63 -> cols [4cg, 4cg+4);  sg = tid >> 6 -> sites [8sg, 8sg+8)
    {
        const int cg = tid & 63;
        const int sg = tid >> 6;
        const int col = 4 * cg;
        ull acc[8][2];
        {
            ulonglong2 bb2 = *(const ulonglong2*)&b2t[col];
            #pragma unroll
            for (int s = 0; s < 8; s++) { acc[s][0] = bb2.x; acc[s][1] = bb2.y; }
        }
        const float* hrow = &hbuf[sg * 8 * HDIM];
        for (int i = 0; i < HDIM; i += 4) {
            ulonglong2 w0 = *(const ulonglong2*)&W2t[(i + 0) * HDIM + col];
            ulonglong2 w1 = *(const ulonglong2*)&W2t[(i + 1) * HDIM + col];
            ulonglong2 w2 = *(const ulonglong2*)&W2t[(i + 2) * HDIM + col];
            ulonglong2 w3 = *(const ulonglong2*)&W2t[(i + 3) * HDIM + col];
            #pragma unroll
            for (int s = 0; s < 8; s++) {
                const float4 h = *(const float4*)&hrow[s * HDIM + i];
                ull hx = dup2(h.x), hy = dup2(h.y), hz = dup2(h.z), hw = dup2(h.w);
                fma2(acc[s][0], hx, w0.x); fma2(acc[s][1], hx, w0.y);
                fma2(acc[s][0], hy, w1.x); fma2(acc[s][1], hy, w1.y);
                fma2(acc[s][0], hz, w2.x); fma2(acc[s][1], hz, w2.y);
                fma2(acc[s][0], hw, w3.x); fma2(acc[s][1], hw, w3.y);
            }
        }
        __syncthreads();   // everyone done READING h1 before overwrite
        #pragma unroll
        for (int s = 0; s < 8; s++) {
            float2 lo = unpk(acc[s][0]);
            float2 hi = unpk(acc[s][1]);
            float4 v;
            v.x = tanh_fast(lo.x);
            v.y = tanh_fast(lo.y);
            v.z = tanh_fast(hi.x);
            v.w = tanh_fast(hi.y);
            *(float4*)&hbuf[(sg * 8 + s) * HDIM + col] = v;
        }
        __syncthreads();
    }

    // -------- layer 3: 2 sites x 4 cols per thread (48 cols padded to 64) ----
    {
        const int cg3 = tid & 15;
        const int sg3 = tid >> 4;
        const int col  = 4 * cg3;
        const bool valid = (col < 48);
        const int colc = valid ? col : 0;
        ull acc3[2][2];
        {
            ulonglong2 bb2 = *(const ulonglong2*)&b3t[colc];
            #pragma unroll
            for (int q = 0; q < 2; q++) { acc3[q][0] = bb2.x; acc3[q][1] = bb2.y; }
        }
        const float* hrow = &hbuf[sg3 * 2 * HDIM];
        for (int i = 0; i < HDIM; i += 4) {
            ulonglong2 w0 = *(const ulonglong2*)&W3t[(i + 0) * 48 + colc];
            ulonglong2 w1 = *(const ulonglong2*)&W3t[(i + 1) * 48 + colc];
            ulonglong2 w2 = *(const ulonglong2*)&W3t[(i + 2) * 48 + colc];
            ulonglong2 w3 = *(const ulonglong2*)&W3t[(i + 3) * 48 + colc];
            #pragma unroll
            for (int q = 0; q < 2; q++) {
                const float4 h = *(const float4*)&hrow[q * HDIM + i];
                ull hx = dup2(h.x), hy = dup2(h.y), hz = dup2(h.z), hw = dup2(h.w);
                fma2(acc3[q][0], hx, w0.x); fma2(acc3[q][1], hx, w0.y);
                fma2(acc3[q][0], hy, w1.x); fma2(acc3[q][1], hy, w1.y);
                fma2(acc3[q][0], hz, w2.x); fma2(acc3[q][1], hz, w2.y);
                fma2(acc3[q][0], hw, w3.x); fma2(acc3[q][1], hw, w3.y);
            }
        }
        if (valid) {
            #pragma unroll
            for (int q = 0; q < 2; q++) {
                float2 lo = unpk(acc3[q][0]);
                float2 hi = unpk(acc3[q][1]);
                float4 v;
                v.x = lo.x; v.y = lo.y; v.z = hi.x; v.w = hi.y;
                *(float4*)&pbuf[(sg3 * 2 + q) * 48 + col] = v;
            }
        }
    }
    __syncthreads();

    // -------- epilogue: mixture transform, one thread per site ----------
    float ldj = 0.f;
    if (tid < TM) {
        const int s = tid;
        const float* pr = &pbuf[s * 48];
        float lgt = lgs[s], sv = svs[s];
        float m = -1e30f;
        #pragma unroll
        for (int k = 0; k < KMIX; k++) m = fmaxf(m, pr[32 + k]);
        float es[KMIX]; float se = 0.f;
        #pragma unroll
        for (int k = 0; k < KMIX; k++) { es[k] = __expf(pr[32 + k] - m); se += es[k]; }
        float inv_se = 1.f / se;
        float y = 0.f, dsum = 0.f;
        #pragma unroll
        for (int k = 0; k < KMIX; k++) {
            float wgt   = fmaf(es[k] * inv_se, 0.84f, 0.01f);
            float alpha = __expf(pr[k]);
            float x     = alpha * (lgt + pr[16 + k]);
            float g     = 1.f / (1.f + __expf(-x));
            y    = fmaf(wgt, g, y);
            dsum = fmaf(wgt * alpha, g * (1.f - g), dsum);
        }
        float dy_du = dsum / (sv * (1.f - sv)) * dsds[s];
        ldj = logf(dy_du);
        int jj  = chunk * TM + s;
        int idx = 3 * jj + off;
        g_z[b * LLEN + idx] = mod2pi(fmaf(TWO_PI_F, y, zrs[s]));
    }
    // deterministic warp reduce (tid<32 == warp 0)
    if (tid < 32) {
        #pragma unroll
        for (int o = 16; o; o >>= 1) ldj += __shfl_down_sync(0xffffffff, ldj, o);
        if (tid == 0) g_part[t * CTAS + blockIdx.x] = ldj;
    }
}

__global__ void final_kernel(float* __restrict__ out, int out_size) {
    int i = blockIdx.x * blockDim.x + threadIdx.x;
    if (i < BATCH * LLEN && i < out_size) out[i] = g_z[i];
    if (blockIdx.x == 0 && threadIdx.x < BATCH) {
        int o = BATCH * LLEN + threadIdx.x;
        if (o < out_size) {
            float s = 0.f;
            for (int t = 0; t < NT; t++)
                for (int c = 0; c < CHUNKS; c++)
                    s += g_part[t * CTAS + threadIdx.x * CHUNKS + c];
            out[o] = s;
        }
    }
}

extern "C" void kernel_launch(void* const* d_in, const int* in_sizes, int n_in,
                              void* d_out, int out_size) {
    const float* z  = (const float*)d_in[0];
    const float* W1 = (const float*)d_in[1];
    const float* b1 = (const float*)d_in[2];
    const float* W2 = (const float*)d_in[3];
    const float* b2 = (const float*)d_in[4];
    const float* W3 = (const float*)d_in[5];
    const float* b3 = (const float*)d_in[6];
    float* out = (float*)d_out;

    init_kernel<<<(BATCH * LLEN + 255) / 256, 256>>>(z);
    for (int t = 0; t < NT; t++) {
        const int off_tab[3] = {0, 2, 1};
        int off = off_tab[t % 3];
        step_kernel<<<CTAS, THREADS>>>(W1, b1, W2, b2, W3, b3, t, off);
    }
    final_kernel<<<(BATCH * LLEN + 255) / 256, 256>>>(out, out_size);
}

// round 6
// speedup vs baseline: 2.1106x; 2.1065x over previous
#include <cuda_runtime.h>
#include <cuda_bf16.h>
#include <math.h>
#include <stdint.h>

#define TWO_PI_F   6.283185307179586f
#define INV_TWO_PI 0.15915494309189535f
#define NT    12
#define KMIX  16
#define HDIM  256
#define LLEN  3072
#define BATCH 64
#define EPSF  1e-6f
#define MCTA  128
#define GRID  512
#define THREADS 256

#define APITCH  1040
#define OFF_A   0
#define B2PITCH 272
#define B2PLANE (32*272)
#define OFF_B2_0 133120
#define OFF_B2_1 150528
#define B3PITCH 144
#define B3PLANE (128*144)
#define OFF_B3  167936
#define OFF_PB  133120
#define OFF_C1  204800
#define OFF_C2  205312
#define OFF_B2S 205824
#define OFF_B3S 206848
#define OFF_LDJP 207040
#define SMEM_DYN 207872

__device__ float g_z[BATCH * LLEN];
__device__ float g_part[NT * GRID];
__device__ __align__(16) __nv_bfloat16 g_w2hi[NT * 256 * 256];
__device__ __align__(16) __nv_bfloat16 g_w2lo[NT * 256 * 256];
__device__ __align__(16) __nv_bfloat16 g_w3hi[NT * 256 * 64];
__device__ __align__(16) __nv_bfloat16 g_w3lo[NT * 256 * 64];

__device__ __forceinline__ float mod2pi(float x) {
    float r = fmodf(x, TWO_PI_F);
    return (r < 0.f) ? r + TWO_PI_F : r;
}
__device__ __forceinline__ float tanh_fast(float x) {
    float y; asm("tanh.approx.f32 %0, %1;" : "=f"(y) : "f"(x)); return y;
}
__device__ __forceinline__ uint32_t smem_u32(const void* p) {
    uint32_t a;
    asm("{ .reg .u64 t; cvta.to.shared.u64 t, %1; cvt.u32.u64 %0, t; }" : "=r"(a) : "l"(p));
    return a;
}
__device__ __forceinline__ uint32_t pack2bf(float a, float b) {
    __nv_bfloat162 h = __floats2bfloat162_rn(a, b);
    return *(uint32_t*)&h;
}

#define MMA(C, A, B0, B1) \
    asm volatile("mma.sync.aligned.m16n8k16.row.col.f32.bf16.bf16.f32 " \
        "{%0,%1,%2,%3},{%4,%5,%6,%7},{%8,%9},{%0,%1,%2,%3};" \
        : "+f"((C)[0]), "+f"((C)[1]), "+f"((C)[2]), "+f"((C)[3]) \
        : "r"((A)[0]), "r"((A)[1]), "r"((A)[2]), "r"((A)[3]), "r"(B0), "r"(B1))
#define LDSM4(R, a) \
    asm volatile("ldmatrix.sync.aligned.m8n8.x4.shared.b16 {%0,%1,%2,%3}, [%4];" \
        : "=r"((R)[0]), "=r"((R)[1]), "=r"((R)[2]), "=r"((R)[3]) : "r"(a))
#define LDSM4T(R, a) \
    asm volatile("ldmatrix.sync.aligned.m8n8.x4.trans.shared.b16 {%0,%1,%2,%3}, [%4];" \
        : "=r"((R)[0]), "=r"((R)[1]), "=r"((R)[2]), "=r"((R)[3]) : "r"(a))
#define CPASYNC16(d, s) asm volatile("cp.async.ca.shared.global [%0], [%1], 16;" :: "r"(d), "l"(s))
#define CPCOMMIT()      asm volatile("cp.async.commit_group;" ::: "memory")
#define CPWAIT0()       asm volatile("cp.async.wait_group 0;" ::: "memory")

__global__ void prep_w2(const float* __restrict__ W2) {
    int i = blockIdx.x * blockDim.x + threadIdx.x;
    if (i >= NT * 256 * 256) return;
    float v = W2[i];
    __nv_bfloat16 hi = __float2bfloat16(v);
    g_w2hi[i] = hi;
    g_w2lo[i] = __float2bfloat16(v - __bfloat162float(hi));
}
__global__ void prep_w3(const float* __restrict__ W3) {
    int i = blockIdx.x * blockDim.x + threadIdx.x;
    if (i >= NT * 256 * 64) return;
    int n = i & 63, k = (i >> 6) & 255, t = i >> 14;
    float v = (n < 48) ? W3[((size_t)t * 256 + k) * 48 + n] : 0.f;
    __nv_bfloat16 hi = __float2bfloat16(v);
    g_w3hi[i] = hi;
    g_w3lo[i] = __float2bfloat16(v - __bfloat162float(hi));
}
__global__ void init_kernel(const float* __restrict__ z_in) {
    int i = blockIdx.x * blockDim.x + threadIdx.x;
    if (i < BATCH * LLEN) g_z[i] = z_in[i];
}

__global__ __launch_bounds__(THREADS, 1)
void step_kernel(const float* __restrict__ W1, const float* __restrict__ b1,
                 const float* __restrict__ b2, const float* __restrict__ b3,
                 int t, int off)
{
    extern __shared__ __align__(16) char dsm[];
    const uint32_t base = smem_u32(dsm);
    char* gb = dsm;

    const int tid  = threadIdx.x;
    const int lane = tid & 31;
    const int wp   = tid >> 5;
    const int blk  = blockIdx.x;
    const int bat  = blk >> 3;
    const int chnk = blk & 7;

    const float* W1t = W1 + t * 2 * HDIM;
    const float* b1t = b1 + t * HDIM;
    const float* zrow = g_z + bat * LLEN;

    // small smem loads
    if (tid < 64) {
        *(float4*)(gb + OFF_B2S + tid * 16) = __ldg((const float4*)&b2[t * 256 + tid * 4]);
    } else if (tid < 76) {
        *(float4*)(gb + OFF_B3S + (tid - 64) * 16) = __ldg((const float4*)&b3[t * 48 + (tid - 64) * 4]);
    }

    // ---- phase 0: per-site context (tid < 128 = site) ----
    float sv = 0.f, dsdu = 0.f, lgt = 0.f, zr = 0.f;
    if (tid < MCTA) {
        int idx = 3 * (chnk * MCTA + tid) + off;
        int im2 = idx - 2; if (im2 < 0) im2 += LLEN;
        int im1 = idx - 1; if (im1 < 0) im1 += LLEN;
        int ip1 = idx + 1; if (ip1 >= LLEN) ip1 -= LLEN;
        int ip2 = idx + 2; if (ip2 >= LLEN) ip2 -= LLEN;
        float zm2 = zrow[im2], zm1 = zrow[im1], z0 = zrow[idx];
        float zp1 = zrow[ip1], zp2 = zrow[ip2];
        *(float*)(gb + OFF_C1 + tid * 4) = mod2pi(zm1 - zm2);
        *(float*)(gb + OFF_C2 + tid * 4) = mod2pi(zp2 - zp1);
        float Vc = mod2pi(z0 - zm1);
        float u = fminf(fmaxf(Vc * INV_TWO_PI, EPSF), 1.f - EPSF);
        float a = u * u, bb = (1.f - u) * (1.f - u);
        float den = a + bb;
        sv = a / den;
        dsdu = 2.f * u * (1.f - u) / (den * den);
        sv = fminf(fmaxf(sv, EPSF), 1.f - EPSF);
        lgt = logf(sv) - log1pf(-sv);
        zr = zm1;
    }
    __syncthreads();

    // ---- layer 1: h1 -> A tile (hi/lo split), thread = (col pair p, s-half) ----
    {
        const int p = tid & 127, sh = tid >> 7;
        float w00 = __ldg(&W1t[2 * p]),       w01 = __ldg(&W1t[2 * p + 1]);
        float w10 = __ldg(&W1t[256 + 2 * p]), w11 = __ldg(&W1t[256 + 2 * p + 1]);
        float bb0 = __ldg(&b1t[2 * p]),       bb1 = __ldg(&b1t[2 * p + 1]);
        for (int s = sh * 64; s < sh * 64 + 64; s++) {
            float c1 = *(const float*)(gb + OFF_C1 + s * 4);
            float c2 = *(const float*)(gb + OFF_C2 + s * 4);
            float x0 = tanh_fast(fmaf(c1, w00, fmaf(c2, w10, bb0)));
            float x1 = tanh_fast(fmaf(c1, w01, fmaf(c2, w11, bb1)));
            __nv_bfloat16 h0 = __float2bfloat16(x0), h1v = __float2bfloat16(x1);
            float l0 = x0 - __bfloat162float(h0), l1 = x1 - __bfloat162float(h1v);
            *(uint32_t*)(gb + OFF_A + s * APITCH + 4 * p)       = pack2bf(x0, x1);
            *(uint32_t*)(gb + OFF_A + s * APITCH + 512 + 4 * p) = pack2bf(l0, l1);
        }
    }
    __syncthreads();

    // ---- lane-derived ldmatrix addresses ----
    const int rA  = wp * 16 + ((lane >> 3) & 1) * 8 + (lane & 7);
    const uint32_t aBase = base + OFF_A + rA * APITCH + ((lane >> 4) * 8) * 2;
    const int krl = ((lane >> 3) & 1) * 8 + (lane & 7);
    const int nc8 = (lane >> 4) * 8;

    float c3a[8][4];
    #pragma unroll
    for (int i = 0; i < 8; i++) { c3a[i][0] = 0.f; c3a[i][1] = 0.f; c3a[i][2] = 0.f; c3a[i][3] = 0.f; }

    #pragma unroll 1
    for (int nh = 0; nh < 2; nh++) {
        float cacc[16][4];
        #pragma unroll
        for (int i = 0; i < 16; i++) { cacc[i][0]=0.f; cacc[i][1]=0.f; cacc[i][2]=0.f; cacc[i][3]=0.f; }

        // prefetch B3 half + B2 chunk 0
        for (int i = tid; i < 2048; i += THREADS) {
            int p = i >> 10, r = (i >> 3) & 127, seg = i & 7;
            const __nv_bfloat16* src = (p ? g_w3lo : g_w3hi) +
                ((size_t)(t * 256 + nh * 128 + r) * 64 + seg * 8);
            CPASYNC16(base + OFF_B3 + p * B3PLANE + r * B3PITCH + seg * 16, src);
        }
        for (int i = tid; i < 1024; i += THREADS) {
            int p = i >> 9, r = (i >> 4) & 31, seg = i & 15;
            const __nv_bfloat16* src = (p ? g_w2lo : g_w2hi) +
                ((size_t)(t * 256 + r) * 256 + nh * 128 + seg * 8);
            CPASYNC16(base + OFF_B2_0 + p * B2PLANE + r * B2PITCH + seg * 16, src);
        }
        CPCOMMIT();
        CPWAIT0();
        __syncthreads();

        #pragma unroll 1
        for (int c = 0; c < 8; c++) {
            const uint32_t bufc = (c & 1) ? (base + OFF_B2_1) : (base + OFF_B2_0);
            if (c < 7) {
                const uint32_t bufn = ((c + 1) & 1) ? (base + OFF_B2_1) : (base + OFF_B2_0);
                for (int i = tid; i < 1024; i += THREADS) {
                    int p = i >> 9, r = (i >> 4) & 31, seg = i & 15;
                    const __nv_bfloat16* src = (p ? g_w2lo : g_w2hi) +
                        ((size_t)(t * 256 + (c + 1) * 32 + r) * 256 + nh * 128 + seg * 8);
                    CPASYNC16(bufn + p * B2PLANE + r * B2PITCH + seg * 16, src);
                }
                CPCOMMIT();
            }
            #pragma unroll
            for (int s = 0; s < 2; s++) {
                const int k = c * 32 + s * 16;
                uint32_t ahi[4], alo[4];
                LDSM4(ahi, aBase + k * 2);
                LDSM4(alo, aBase + k * 2 + 512);
                const uint32_t brow = bufc + (s * 16 + krl) * B2PITCH + nc8 * 2;
                #pragma unroll
                for (int ntp = 0; ntp < 8; ntp++) {
                    uint32_t bh[4], bl[4];
                    LDSM4T(bh, brow + ntp * 32);
                    LDSM4T(bl, brow + ntp * 32 + B2PLANE);
                    MMA(cacc[2 * ntp],     ahi, bh[0], bh[1]);
                    MMA(cacc[2 * ntp + 1], ahi, bh[2], bh[3]);
                    MMA(cacc[2 * ntp],     ahi, bl[0], bl[1]);
                    MMA(cacc[2 * ntp + 1], ahi, bl[2], bl[3]);
                    MMA(cacc[2 * ntp],     alo, bh[0], bh[1]);
                    MMA(cacc[2 * ntp + 1], alo, bh[2], bh[3]);
                }
            }
            CPWAIT0();
            __syncthreads();
        }

        // ---- convert C2 -> h2 A-fragments in registers ----
        uint32_t ahi3[8][4], alo3[8][4];
        #pragma unroll
        for (int j = 0; j < 8; j++) {
            #pragma unroll
            for (int h = 0; h < 2; h++) {
                const int tile = 2 * j + h;
                const int colg = nh * 128 + tile * 8 + (lane & 3) * 2;
                float2 bb = *(const float2*)(gb + OFF_B2S + colg * 4);
                float x0 = tanh_fast(cacc[tile][0] + bb.x);
                float x1 = tanh_fast(cacc[tile][1] + bb.y);
                float x2 = tanh_fast(cacc[tile][2] + bb.x);
                float x3 = tanh_fast(cacc[tile][3] + bb.y);
                __nv_bfloat16 q0 = __float2bfloat16(x0), q1 = __float2bfloat16(x1);
                __nv_bfloat16 q2 = __float2bfloat16(x2), q3 = __float2bfloat16(x3);
                ahi3[j][2 * h]     = pack2bf(x0, x1);
                ahi3[j][2 * h + 1] = pack2bf(x2, x3);
                alo3[j][2 * h]     = pack2bf(x0 - __bfloat162float(q0), x1 - __bfloat162float(q1));
                alo3[j][2 * h + 1] = pack2bf(x2 - __bfloat162float(q2), x3 - __bfloat162float(q3));
            }
        }
        // ---- GEMM3 partial (k = this half's 128 cols of h2) ----
        #pragma unroll
        for (int j = 0; j < 8; j++) {
            const uint32_t b3row = base + OFF_B3 + (j * 16 + krl) * B3PITCH + nc8 * 2;
            #pragma unroll
            for (int np = 0; np < 4; np++) {
                uint32_t bh[4], bl[4];
                LDSM4T(bh, b3row + np * 32);
                LDSM4T(bl, b3row + np * 32 + B3PLANE);
                MMA(c3a[2 * np],     ahi3[j], bh[0], bh[1]);
                MMA(c3a[2 * np + 1], ahi3[j], bh[2], bh[3]);
                MMA(c3a[2 * np],     ahi3[j], bl[0], bl[1]);
                MMA(c3a[2 * np + 1], ahi3[j], bl[2], bl[3]);
                MMA(c3a[2 * np],     alo3[j], bh[0], bh[1]);
                MMA(c3a[2 * np + 1], alo3[j], bh[2], bh[3]);
            }
        }
        __syncthreads();
    }

    // ---- store params to pbuf ----
    {
        const int r0 = wp * 16 + (lane >> 2);
        const int cb = (lane & 3) * 2;
        #pragma unroll
        for (int tl = 0; tl < 8; tl++) {
            float2 v01 = make_float2(c3a[tl][0], c3a[tl][1]);
            float2 v23 = make_float2(c3a[tl][2], c3a[tl][3]);
            *(float2*)(gb + OFF_PB + (r0 * 64 + tl * 8 + cb) * 4)       = v01;
            *(float2*)(gb + OFF_PB + ((r0 + 8) * 64 + tl * 8 + cb) * 4) = v23;
        }
    }
    __syncthreads();

    // ---- epilogue ----
    float ldj = 0.f;
    if (tid < MCTA) {
        const float* pr  = (const float*)(gb + OFF_PB) + tid * 64;
        const float* b3s = (const float*)(gb + OFF_B3S);
        float m = -1e30f, wl[KMIX];
        #pragma unroll
        for (int k = 0; k < KMIX; k++) { wl[k] = pr[32 + k] + b3s[32 + k]; m = fmaxf(m, wl[k]); }
        float se = 0.f, es[KMIX];
        #pragma unroll
        for (int k = 0; k < KMIX; k++) { es[k] = __expf(wl[k] - m); se += es[k]; }
        float inv_se = 1.f / se;
        float y = 0.f, dsum = 0.f;
        #pragma unroll
        for (int k = 0; k < KMIX; k++) {
            float lsc = pr[k] + b3s[k];
            float shf = pr[16 + k] + b3s[16 + k];
            float wgt = fmaf(es[k] * inv_se, 0.84f, 0.01f);
            float alpha = __expf(lsc);
            float xx = alpha * (lgt + shf);
            float g = 1.f / (1.f + __expf(-xx));
            y = fmaf(wgt, g, y);
            dsum = fmaf(wgt * alpha, g * (1.f - g), dsum);
        }
        float dy_du = dsum / (sv * (1.f - sv)) * dsdu;
        ldj = logf(dy_du);
        int idx = 3 * (chnk * MCTA + tid) + off;
        g_z[bat * LLEN + idx] = mod2pi(fmaf(TWO_PI_F, y, zr));
        #pragma unroll
        for (int o = 16; o; o >>= 1) ldj += __shfl_down_sync(0xffffffff, ldj, o);
        if (lane == 0) *(float*)(gb + OFF_LDJP + wp * 4) = ldj;
    }
    __syncthreads();
    if (tid == 0) {
        float s = 0.f;
        #pragma unroll
        for (int i = 0; i < 4; i++) s += *(const float*)(gb + OFF_LDJP + i * 4);
        g_part[t * GRID + blk] = s;
    }
}

__global__ void final_kernel(float* __restrict__ out, int out_size) {
    int i = blockIdx.x * blockDim.x + threadIdx.x;
    if (i < BATCH * LLEN && i < out_size) out[i] = g_z[i];
    if (blockIdx.x == 0 && threadIdx.x < BATCH) {
        int o = BATCH * LLEN + threadIdx.x;
        if (o < out_size) {
            float s = 0.f;
            for (int t = 0; t < NT; t++)
                for (int c = 0; c < 8; c++)
                    s += g_part[t * GRID + threadIdx.x * 8 + c];
            out[o] = s;
        }
    }
}

extern "C" void kernel_launch(void* const* d_in, const int* in_sizes, int n_in,
                              void* d_out, int out_size) {
    const float* z  = (const float*)d_in[0];
    const float* W1 = (const float*)d_in[1];
    const float* b1 = (const float*)d_in[2];
    const float* W2 = (const float*)d_in[3];
    const float* b2 = (const float*)d_in[4];
    const float* W3 = (const float*)d_in[5];
    const float* b3 = (const float*)d_in[6];
    float* out = (float*)d_out;

    static int attr_set = 0;
    if (!attr_set) {
        cudaFuncSetAttribute(step_kernel, cudaFuncAttributeMaxDynamicSharedMemorySize, SMEM_DYN);
        attr_set = 1;
    }

    prep_w2<<<(NT * 256 * 256 + 255) / 256, 256>>>(W2);
    prep_w3<<<(NT * 256 * 64 + 255) / 256, 256>>>(W3);
    init_kernel<<<(BATCH * LLEN + 255) / 256, 256>>>(z);
    for (int t = 0; t < NT; t++) {
        const int off_tab[3] = {0, 2, 1};
        step_kernel<<<GRID, THREADS, SMEM_DYN>>>(W1, b1, b2, b3, t, off_tab[t % 3]);
    }
    final_kernel<<<(BATCH * LLEN + 255) / 256, 256>>>(out, out_size);
}